// round 9
// baseline (speedup 1.0000x reference)
#include <cuda_runtime.h>
#include <cuda_bf16.h>
#include <math.h>

#define NCOMP 32
#define NLAT  64
#define MAXC  512
#define MAXG  4000
#define MAXCUT 1048576

// Scratch (static device arrays — no runtime allocation)
static __device__ __nv_bfloat16 g_deltab[(size_t)MAXC * MAXG * NCOMP]; // 131 MB, logits (delta + logit0) bf16
static __device__ float  g_counts[MAXC * MAXG];                  // 8.2 MB
static __device__ float2 g_tab2[MAXG * NCOMP];                   // {loc, inv_scale}
static __device__ float  g_tabw[MAXG * NCOMP];                   // -log(scale)-0.5*log(2pi)
static __device__ __nv_bfloat16 g_l0b[MAXG * NCOMP];             // gathered logit_w bf16
static __device__ float  g_grw[MAXG * NLAT];                     // gathered rho_weight
static __device__ float  g_latT[NLAT * MAXC];                    // latent transposed [l][cell]
static __device__ __nv_bfloat16 g_latb[MAXC * NLAT];             // latent bf16 [cell][l]
static __device__ __nv_bfloat16 g_lwb[(size_t)MAXG * NCOMP * NLAT]; // weights bf16 [g][c][k] (K-major)
static __device__ float  g_logrb[MAXG];
static __device__ float  g_rb[MAXG];
static __device__ float  g_lib[MAXC];
static __device__ float  g_loglib[MAXC];
static __device__ int    g_hist[MAXG];
static __device__ int    g_off[MAXG];
static __device__ uint4  g_scut[MAXCUT];                         // sorted: {pair, coord_bits, gene, 0}
static __device__ double g_acc;

// ---------------- init / scatter / hist ----------------
__global__ void k_init(int n) {
    int stride = gridDim.x * blockDim.x;
    for (int i = blockIdx.x * blockDim.x + threadIdx.x; i < n; i += stride)
        g_counts[i] = 0.0f;
    for (int i = blockIdx.x * blockDim.x + threadIdx.x; i < MAXG; i += stride)
        g_hist[i] = 0;
    if (blockIdx.x == 0 && threadIdx.x == 0) g_acc = 0.0;
}

__global__ void k_scatter(const int* __restrict__ ix, int n) {
    int i = blockIdx.x * blockDim.x + threadIdx.x;
    if (i < n) atomicAdd(&g_counts[ix[i]], 1.0f);
}

__global__ void k_hist(const int* __restrict__ cgx, int n) {
    __shared__ int h[MAXG];
    for (int i = threadIdx.x; i < MAXG; i += blockDim.x) h[i] = 0;
    __syncthreads();
    int stride = gridDim.x * blockDim.x;
    for (int i = blockIdx.x * blockDim.x + threadIdx.x; i < n; i += stride)
        atomicAdd(&h[cgx[i]], 1);
    __syncthreads();
    for (int i = threadIdx.x; i < MAXG; i += blockDim.x)
        if (h[i]) atomicAdd(&g_hist[i], h[i]);
}

// Exclusive scan of g_hist -> g_off. One block, 1024 threads, 4 bins/thread.
__global__ void k_scan() {
    __shared__ int ps[1024];
    int t = threadIdx.x;
    int v[4];
    int s = 0;
#pragma unroll
    for (int j = 0; j < 4; j++) {
        int b = t * 4 + j;
        v[j] = (b < MAXG) ? g_hist[b] : 0;
        s += v[j];
    }
    ps[t] = s;
    __syncthreads();
    for (int off = 1; off < 1024; off <<= 1) {
        int x = (t >= off) ? ps[t - off] : 0;
        __syncthreads();
        ps[t] += x;
        __syncthreads();
    }
    int base = ps[t] - s;  // exclusive
#pragma unroll
    for (int j = 0; j < 4; j++) {
        int b = t * 4 + j;
        if (b < MAXG) g_off[b] = base;
        base += v[j];
    }
}

__global__ void k_ssort(const int* __restrict__ cpx, const int* __restrict__ cgx,
                        const float* __restrict__ coord, int n) {
    int i = blockIdx.x * blockDim.x + threadIdx.x;
    if (i < n) {
        int g = cgx[i];
        int p = atomicAdd(&g_off[g], 1);
        g_scut[p] = make_uint4((unsigned)cpx[i], __float_as_uint(coord[i]), (unsigned)g, 0u);
    }
}

// ---------------- prep ----------------
__global__ void k_prep(const float* __restrict__ loc_w, const float* __restrict__ scale_w,
                       const float* __restrict__ logit_w, const float* __restrict__ rho_weight,
                       const float* __restrict__ rho_bias, const float* __restrict__ libsize,
                       const float* __restrict__ latent, const int* __restrict__ genes_oi,
                       const int* __restrict__ cells_oi, int n_genes, int n_cells) {
    int total = n_genes * NCOMP + n_genes * NLAT + n_genes + n_cells * NLAT + n_cells;
    int stride = gridDim.x * blockDim.x;
    for (int i = blockIdx.x * blockDim.x + threadIdx.x; i < total; i += stride) {
        int r = i;
        if (r < n_genes * NCOMP) {
            int g = r / NCOMP, c = r % NCOMP;
            int tg = genes_oi[g];
            float lw = loc_w[(size_t)tg * NCOMP + c];
            float sw = scale_w[(size_t)tg * NCOMP + c];
            float lg = logit_w[(size_t)tg * NCOMP + c];
            float loc = 1.0f / (1.0f + expf(-lw));
            float scale = 1e-5f + expf(sw);
            g_tab2[r] = make_float2(loc, 1.0f / scale);
            g_tabw[r] = -logf(scale) - 0.91893853320467274f;
            g_l0b[r] = __float2bfloat16(lg);
            continue;
        }
        r -= n_genes * NCOMP;
        if (r < n_genes * NLAT) {
            int g = r / NLAT, l = r % NLAT;
            g_grw[r] = rho_weight[(size_t)genes_oi[g] * NLAT + l];
            continue;
        }
        r -= n_genes * NLAT;
        if (r < n_genes) {
            float rb = rho_bias[genes_oi[r]];
            g_rb[r] = rb;
            g_logrb[r] = logf(rb);
            continue;
        }
        r -= n_genes;
        if (r < n_cells * NLAT) {
            int l = r / n_cells, cell = r % n_cells;
            float v = latent[(size_t)cell * NLAT + l];
            g_latT[r] = v;                                   // [l][cell]
            g_latb[(size_t)cell * NLAT + l] = __float2bfloat16(v);
            continue;
        }
        r -= n_cells * NLAT;
        {
            float lb = libsize[cells_oi[r]];
            g_lib[r] = lb;
            g_loglib[r] = logf(lb);
        }
    }
}

// Transpose+convert gathered weights: g_lwb[g][c][k] = bf16(logit_weight[tg][k][c])
__global__ void k_tr(const float* __restrict__ logit_weight, const int* __restrict__ genes_oi) {
    __shared__ float ts[NLAT][NCOMP + 1];
    int g = blockIdx.x;
    int tg = genes_oi[g];
    const float4* src = (const float4*)(logit_weight + (size_t)tg * (NLAT * NCOMP));
    int tid = threadIdx.x;
#pragma unroll
    for (int it = 0; it < 2; it++) {
        int i = it * 256 + tid;            // 512 float4 chunks
        float4 v = src[i];
        int k = i >> 3, c4 = (i & 7) * 4;  // row k, cols c4..c4+3
        ts[k][c4] = v.x; ts[k][c4 + 1] = v.y; ts[k][c4 + 2] = v.z; ts[k][c4 + 3] = v.w;
    }
    __syncthreads();
    __nv_bfloat162* dst = (__nv_bfloat162*)(g_lwb + (size_t)g * (NCOMP * NLAT));
#pragma unroll
    for (int it = 0; it < 4; it++) {
        int i = it * 256 + tid;            // 1024 bf16x2 outputs: c = i>>5, k2 = (i&31)*2
        int c = i >> 5, k2 = (i & 31) * 2;
        dst[i] = __floats2bfloat162_rn(ts[k2][c], ts[k2 + 1][c]);
    }
}

// ---------------- mma.sync bf16 GEMM: logits = latent @ W + logit0 ----------------
#define ASTRIDE 72   // padded A/B row stride (bf16)
#define CSTRIDE 136  // padded C stage row stride (bf16)

__device__ __forceinline__ void mma_bf16(float* c, const unsigned* a, const unsigned* b) {
    asm volatile(
        "mma.sync.aligned.m16n8k16.row.col.f32.bf16.bf16.f32 "
        "{%0,%1,%2,%3}, {%4,%5,%6,%7}, {%8,%9}, {%0,%1,%2,%3};"
        : "+f"(c[0]), "+f"(c[1]), "+f"(c[2]), "+f"(c[3])
        : "r"(a[0]), "r"(a[1]), "r"(a[2]), "r"(a[3]), "r"(b[0]), "r"(b[1]));
}

__global__ void __launch_bounds__(256) k_gemm_mma(int n_cells, int n_genes) {
    __shared__ __align__(16) char smraw[2 * 128 * ASTRIDE * 2];  // 36864 B
    __nv_bfloat16* As = (__nv_bfloat16*)smraw;
    __nv_bfloat16* Bs = As + 128 * ASTRIDE;
    __nv_bfloat16* Cs = (__nv_bfloat16*)smraw;  // reused after compute (34816 B)

    int tid = threadIdx.x;
    int gbase = blockIdx.x * 4;     // 4 genes -> 128 output cols
    int cbase = blockIdx.y * 128;   // 128 cells

    const uint4* asrc = (const uint4*)(g_latb + (size_t)cbase * NLAT);
    const uint4* bsrc = (const uint4*)(g_lwb + (size_t)gbase * (NCOMP * NLAT));
#pragma unroll
    for (int i = 0; i < 4; i++) {
        int cid = i * 256 + tid;
        int row = cid >> 3, ch = cid & 7;
        *(uint4*)(As + row * ASTRIDE + ch * 8) = asrc[cid];
        *(uint4*)(Bs + row * ASTRIDE + ch * 8) = bsrc[cid];
    }
    __syncthreads();

    int wid = tid >> 5, lane = tid & 31;
    int wm = (wid & 3) * 32;
    int wn = (wid >> 2) * 64;
    int g = lane >> 2, t = lane & 3;

    float acc[2][8][4];
#pragma unroll
    for (int mt = 0; mt < 2; mt++)
#pragma unroll
        for (int nt = 0; nt < 8; nt++)
#pragma unroll
            for (int j = 0; j < 4; j++) acc[mt][nt][j] = 0.0f;

#pragma unroll
    for (int kc = 0; kc < 4; kc++) {
        int k0 = kc * 16;
        unsigned a[2][4];
#pragma unroll
        for (int mt = 0; mt < 2; mt++) {
            int r0 = wm + mt * 16 + g;
            a[mt][0] = *(const unsigned*)(As + (r0)     * ASTRIDE + k0 + 2 * t);
            a[mt][1] = *(const unsigned*)(As + (r0 + 8) * ASTRIDE + k0 + 2 * t);
            a[mt][2] = *(const unsigned*)(As + (r0)     * ASTRIDE + k0 + 2 * t + 8);
            a[mt][3] = *(const unsigned*)(As + (r0 + 8) * ASTRIDE + k0 + 2 * t + 8);
        }
        unsigned b[8][2];
#pragma unroll
        for (int nt = 0; nt < 8; nt++) {
            int n0 = wn + nt * 8 + g;
            b[nt][0] = *(const unsigned*)(Bs + n0 * ASTRIDE + k0 + 2 * t);
            b[nt][1] = *(const unsigned*)(Bs + n0 * ASTRIDE + k0 + 2 * t + 8);
        }
#pragma unroll
        for (int mt = 0; mt < 2; mt++)
#pragma unroll
            for (int nt = 0; nt < 8; nt++)
                mma_bf16(acc[mt][nt], a[mt], b[nt]);
    }
    __syncthreads();  // done with As/Bs; reuse as Cs

    // Stage to smem as bf16 with logit0 added.
#pragma unroll
    for (int nt = 0; nt < 8; nt++) {
        int col = wn + nt * 8 + 2 * t;
        float2 l0 = __bfloat1622float2(*(const __nv_bfloat162*)(g_l0b + gbase * NCOMP + col));
#pragma unroll
        for (int mt = 0; mt < 2; mt++) {
            int r0 = wm + mt * 16 + g;
            *(__nv_bfloat162*)(Cs + r0 * CSTRIDE + col) =
                __floats2bfloat162_rn(acc[mt][nt][0] + l0.x, acc[mt][nt][1] + l0.y);
            *(__nv_bfloat162*)(Cs + (r0 + 8) * CSTRIDE + col) =
                __floats2bfloat162_rn(acc[mt][nt][2] + l0.x, acc[mt][nt][3] + l0.y);
        }
    }
    __syncthreads();

    // Coalesced copy to global: 128 rows x 256B.
    size_t rowstride = (size_t)n_genes * NCOMP;
    __nv_bfloat16* dbase = g_deltab + (size_t)gbase * NCOMP;
#pragma unroll
    for (int it = 0; it < 8; it++) {
        int cid = it * 256 + tid;        // 2048 chunks: row = cid>>4, ch = cid&15
        int row = cid >> 4, ch = cid & 15;
        uint4 v = *(const uint4*)(Cs + row * CSTRIDE + ch * 8);
        *(uint4*)(dbase + (size_t)(cbase + row) * rowstride + ch * 8) = v;
    }
}

// ---------------- Poisson fragment-count likelihood ----------------
__global__ void k_poisson(int n_cells, int n_genes) {
    __shared__ float rw_s[8][NLAT];
    __shared__ float red[8];

    int gbase = blockIdx.x * 8;
    int cell = blockIdx.y * 256 + threadIdx.x;
    int tid = threadIdx.x;

    for (int i = tid; i < 8 * NLAT; i += 256) {
        int j = i / NLAT, l = i % NLAT;
        int g = gbase + j;
        rw_s[j][l] = (g < n_genes) ? g_grw[g * NLAT + l] : 0.0f;
    }
    __syncthreads();

    float lsum = 0.0f;
    if (cell < n_cells) {
        float acc[8] = {0, 0, 0, 0, 0, 0, 0, 0};
#pragma unroll 16
        for (int l = 0; l < NLAT; l++) {
            float lat = g_latT[l * n_cells + cell];
#pragma unroll
            for (int j = 0; j < 8; j++)
                acc[j] = fmaf(lat, rw_s[j][l], acc[j]);
        }
        float lib = g_lib[cell], ll = g_loglib[cell];
#pragma unroll
        for (int j = 0; j < 8; j++) {
            int g = gbase + j;
            if (g >= n_genes) continue;
            float rho = acc[j];
            float fe = g_rb[g] * __expf(rho) * lib;
            float cnt = g_counts[(size_t)cell * n_genes + g];
            float t = cnt * (g_logrb[g] + rho + ll) - fe;
            if (cnt > 1.5f) t -= lgammaf(cnt + 1.0f);
            lsum += t;
        }
    }
    for (int s = 16; s > 0; s >>= 1) lsum += __shfl_xor_sync(0xffffffffu, lsum, s);
    int wid = tid >> 5;
    if ((tid & 31) == 0) red[wid] = lsum;
    __syncthreads();
    if (tid == 0) {
        float s = 0.0f;
        for (int i = 0; i < 8; i++) s += red[i];
        atomicAdd(&g_acc, (double)s);
    }
}

// ---------------- Mixture likelihood: one warp per (gene-sorted) cut ----------------
__global__ void k_mix(int n_cuts) {
    __shared__ float red[8];
    int lane = threadIdx.x & 31;
    int wid = threadIdx.x >> 5;
    int gw = blockIdx.x * 8 + wid;
    int nwarps = gridDim.x * 8;

    float local = 0.0f;
    for (int k = gw; k < n_cuts; k += nwarps) {
        uint4 cc = g_scut[k];
        int pair = (int)cc.x;
        float x = __uint_as_float(cc.y);
        int g = (int)cc.z;
        float2 t2 = g_tab2[g * NCOMP + lane];       // {loc, inv_scale} (L1-hot: sorted by gene)
        float tw = g_tabw[g * NCOMP + lane];
        float logit = __bfloat162float(g_deltab[(size_t)pair * NCOMP + lane]);
        float z = (x - t2.x) * t2.y;
        float a = fmaf(-0.5f * z, z, logit + tw);
        float e1 = __expf(a);
        float e2 = __expf(logit);
#pragma unroll
        for (int s = 16; s > 0; s >>= 1) {
            e1 += __shfl_xor_sync(0xffffffffu, e1, s);
            e2 += __shfl_xor_sync(0xffffffffu, e2, s);
        }
        local += __logf(fmaxf(e1, 1e-37f)) - __logf(e2);
    }
    if (lane == 0) red[wid] = local;
    __syncthreads();
    if (threadIdx.x == 0) {
        float s = 0.0f;
        for (int i = 0; i < 8; i++) s += red[i];
        atomicAdd(&g_acc, (double)s);
    }
}

__global__ void k_final(float* out) {
    out[0] = (float)(-g_acc);
}

extern "C" void kernel_launch(void* const* d_in, const int* in_sizes, int n_in,
                              void* d_out, int out_size) {
    const int*   frag_ix      = (const int*)d_in[0];
    const float* coord        = (const float*)d_in[1];
    const float* latent       = (const float*)d_in[2];
    const int*   genes_oi     = (const int*)d_in[3];
    const int*   cells_oi     = (const int*)d_in[4];
    const int*   cpx          = (const int*)d_in[5];
    const int*   cgx          = (const int*)d_in[6];
    const float* loc_w        = (const float*)d_in[9];
    const float* scale_w      = (const float*)d_in[10];
    const float* logit_w      = (const float*)d_in[11];
    const float* logit_weight = (const float*)d_in[12];
    const float* rho_weight   = (const float*)d_in[13];
    const float* rho_bias     = (const float*)d_in[14];
    const float* libsize      = (const float*)d_in[15];

    int n_frags = in_sizes[0];
    int n_cuts  = in_sizes[1];
    int n_genes = in_sizes[3];
    int n_cells = in_sizes[4];

    k_init<<<512, 256>>>(n_cells * n_genes);
    k_scatter<<<(n_frags + 255) / 256, 256>>>(frag_ix, n_frags);
    k_hist<<<296, 256>>>(cgx, n_cuts);
    k_scan<<<1, 1024>>>();
    k_ssort<<<(n_cuts + 255) / 256, 256>>>(cpx, cgx, coord, n_cuts);
    k_prep<<<1024, 256>>>(loc_w, scale_w, logit_w, rho_weight, rho_bias, libsize,
                          latent, genes_oi, cells_oi, n_genes, n_cells);
    k_tr<<<n_genes, 256>>>(logit_weight, genes_oi);
    dim3 gg(n_genes / 4, n_cells / 128);
    k_gemm_mma<<<gg, 256>>>(n_cells, n_genes);
    dim3 gp((n_genes + 7) / 8, (n_cells + 255) / 256);
    k_poisson<<<gp, 256>>>(n_cells, n_genes);
    k_mix<<<2048, 256>>>(n_cuts);
    k_final<<<1, 1>>>((float*)d_out);
}

// round 10
// speedup vs baseline: 1.2778x; 1.2778x over previous
#include <cuda_runtime.h>
#include <cuda_bf16.h>
#include <math.h>

#define NCOMP 32
#define NLAT  64
#define MAXC  512
#define MAXG  4000
#define MAXCUT 1048576

// Scratch (static device arrays — no runtime allocation)
static __device__ __nv_bfloat16 g_deltab[(size_t)MAXC * MAXG * NCOMP]; // 131 MB, logits (delta + logit0) bf16
static __device__ float  g_ldenom[MAXC * MAXG];                  // 8.2 MB, log(sum(exp(logits))) per pair
static __device__ float  g_counts[MAXC * MAXG];                  // 8.2 MB
static __device__ float  g_loc[MAXG * NCOMP];                    // sigmoid(loc_w)
static __device__ float  g_isc[MAXG * NCOMP];                    // 1/scale
static __device__ float  g_twv[MAXG * NCOMP];                    // -log(scale)-0.5*log(2pi)
static __device__ __nv_bfloat16 g_l0b[MAXG * NCOMP];             // gathered logit_w bf16
static __device__ float  g_grw[MAXG * NLAT];                     // gathered rho_weight
static __device__ float  g_latT[NLAT * MAXC];                    // latent transposed [l][cell]
static __device__ __nv_bfloat16 g_latb[MAXC * NLAT];             // latent bf16 [cell][l]
static __device__ __nv_bfloat16 g_lwb[(size_t)MAXG * NCOMP * NLAT]; // weights bf16 [g][c][k] (K-major)
static __device__ float  g_logrb[MAXG];
static __device__ float  g_rb[MAXG];
static __device__ float  g_lib[MAXC];
static __device__ float  g_loglib[MAXC];
static __device__ int    g_hist[MAXG];
static __device__ int    g_off[MAXG];
static __device__ uint2  g_scut2[MAXCUT];                        // sorted: {pair, gene<<16 | coord16}
static __device__ double g_acc;

// ---------------- init ----------------
__global__ void k_init(int n) {
    int stride = gridDim.x * blockDim.x;
    for (int i = blockIdx.x * blockDim.x + threadIdx.x; i < n; i += stride)
        g_counts[i] = 0.0f;
    for (int i = blockIdx.x * blockDim.x + threadIdx.x; i < MAXG; i += stride)
        g_hist[i] = 0;
    if (blockIdx.x == 0 && threadIdx.x == 0) g_acc = 0.0;
}

// Fragment-count scatter + cut-gene histogram in one kernel.
__global__ void k_scatter(const int* __restrict__ ix, int n_frags,
                          const int* __restrict__ cgx, int n_cuts) {
    int i = blockIdx.x * blockDim.x + threadIdx.x;
    int stride = gridDim.x * blockDim.x;
    for (int k = i; k < n_frags; k += stride) atomicAdd(&g_counts[ix[k]], 1.0f);
    for (int k = i; k < n_cuts; k += stride) atomicAdd(&g_hist[cgx[k]], 1);
}

// Exclusive scan of g_hist -> g_off. One block, 1024 threads, 4 bins/thread, warp-hierarchical.
__global__ void k_scan() {
    __shared__ int wsum[32];
    int t = threadIdx.x, lane = t & 31, wid = t >> 5;
    int v[4], s = 0;
#pragma unroll
    for (int j = 0; j < 4; j++) {
        int b = t * 4 + j;
        v[j] = (b < MAXG) ? g_hist[b] : 0;
        s += v[j];
    }
    int inc = s;
#pragma unroll
    for (int o = 1; o < 32; o <<= 1) {
        int x = __shfl_up_sync(0xffffffffu, inc, o);
        if (lane >= o) inc += x;
    }
    if (lane == 31) wsum[wid] = inc;
    __syncthreads();
    if (wid == 0) {
        int w = wsum[lane];
        int wi = w;
#pragma unroll
        for (int o = 1; o < 32; o <<= 1) {
            int x = __shfl_up_sync(0xffffffffu, wi, o);
            if (lane >= o) wi += x;
        }
        wsum[lane] = wi - w;  // exclusive warp base
    }
    __syncthreads();
    int base = wsum[wid] + inc - s;  // exclusive across all
#pragma unroll
    for (int j = 0; j < 4; j++) {
        int b = t * 4 + j;
        if (b < MAXG) g_off[b] = base;
        base += v[j];
    }
}

__global__ void k_ssort(const int* __restrict__ cpx, const int* __restrict__ cgx,
                        const float* __restrict__ coord, int n) {
    int i = blockIdx.x * blockDim.x + threadIdx.x;
    if (i < n) {
        int g = cgx[i];
        unsigned c16 = (unsigned)(coord[i] * 65535.0f + 0.5f);
        if (c16 > 65535u) c16 = 65535u;
        int p = atomicAdd(&g_off[g], 1);
        g_scut2[p] = make_uint2((unsigned)cpx[i], ((unsigned)g << 16) | c16);
    }
}

// ---------------- prep + weight transpose (fused; grid = n_genes blocks of 256) ----------------
__global__ void k_prep_tr(const float* __restrict__ loc_w, const float* __restrict__ scale_w,
                          const float* __restrict__ logit_w, const float* __restrict__ rho_weight,
                          const float* __restrict__ rho_bias, const float* __restrict__ libsize,
                          const float* __restrict__ latent, const float* __restrict__ logit_weight,
                          const int* __restrict__ genes_oi, const int* __restrict__ cells_oi,
                          int n_genes, int n_cells) {
    // Part 1: per-gene weight transpose [L][C] -> bf16 [C][L]
    __shared__ float ts[NLAT][NCOMP + 1];
    int g = blockIdx.x;
    int tg = genes_oi[g];
    const float4* src = (const float4*)(logit_weight + (size_t)tg * (NLAT * NCOMP));
    int tid = threadIdx.x;
#pragma unroll
    for (int it = 0; it < 2; it++) {
        int i = it * 256 + tid;            // 512 float4 chunks
        float4 v = src[i];
        int k = i >> 3, c4 = (i & 7) * 4;
        ts[k][c4] = v.x; ts[k][c4 + 1] = v.y; ts[k][c4 + 2] = v.z; ts[k][c4 + 3] = v.w;
    }
    __syncthreads();
    __nv_bfloat162* dst = (__nv_bfloat162*)(g_lwb + (size_t)g * (NCOMP * NLAT));
#pragma unroll
    for (int it = 0; it < 4; it++) {
        int i = it * 256 + tid;            // c = i>>5, k2 = (i&31)*2
        int c = i >> 5, k2 = (i & 31) * 2;
        dst[i] = __floats2bfloat162_rn(ts[k2][c], ts[k2 + 1][c]);
    }

    // Part 2: strided slice of remaining prep
    int total = n_genes * NCOMP + n_genes * NLAT + n_genes + n_cells * NLAT + n_cells;
    int stride = gridDim.x * 256;
    for (int i = blockIdx.x * 256 + tid; i < total; i += stride) {
        int r = i;
        if (r < n_genes * NCOMP) {
            int gg = r / NCOMP, c = r % NCOMP;
            int tgg = genes_oi[gg];
            float lw = loc_w[(size_t)tgg * NCOMP + c];
            float sw = scale_w[(size_t)tgg * NCOMP + c];
            float lg = logit_w[(size_t)tgg * NCOMP + c];
            float scale = 1e-5f + expf(sw);
            g_loc[r] = 1.0f / (1.0f + expf(-lw));
            g_isc[r] = 1.0f / scale;
            g_twv[r] = -logf(scale) - 0.91893853320467274f;
            g_l0b[r] = __float2bfloat16(lg);
            continue;
        }
        r -= n_genes * NCOMP;
        if (r < n_genes * NLAT) {
            int gg = r / NLAT, l = r % NLAT;
            g_grw[r] = rho_weight[(size_t)genes_oi[gg] * NLAT + l];
            continue;
        }
        r -= n_genes * NLAT;
        if (r < n_genes) {
            float rb = rho_bias[genes_oi[r]];
            g_rb[r] = rb;
            g_logrb[r] = logf(rb);
            continue;
        }
        r -= n_genes;
        if (r < n_cells * NLAT) {
            int l = r / n_cells, cell = r % n_cells;
            float v = latent[(size_t)cell * NLAT + l];
            g_latT[r] = v;
            g_latb[(size_t)cell * NLAT + l] = __float2bfloat16(v);
            continue;
        }
        r -= n_cells * NLAT;
        {
            float lb = libsize[cells_oi[r]];
            g_lib[r] = lb;
            g_loglib[r] = logf(lb);
        }
    }
}

// ---------------- mma.sync bf16 GEMM: logits = latent @ W + logit0; + per-pair LSE ----------------
#define ASTRIDE 72   // padded A/B row stride (bf16)
#define CSTRIDE 136  // padded C stage row stride (bf16)

__device__ __forceinline__ void mma_bf16(float* c, const unsigned* a, const unsigned* b) {
    asm volatile(
        "mma.sync.aligned.m16n8k16.row.col.f32.bf16.bf16.f32 "
        "{%0,%1,%2,%3}, {%4,%5,%6,%7}, {%8,%9}, {%0,%1,%2,%3};"
        : "+f"(c[0]), "+f"(c[1]), "+f"(c[2]), "+f"(c[3])
        : "r"(a[0]), "r"(a[1]), "r"(a[2]), "r"(a[3]), "r"(b[0]), "r"(b[1]));
}

__global__ void __launch_bounds__(256) k_gemm_mma(int n_cells, int n_genes) {
    __shared__ __align__(16) char smraw[2 * 128 * ASTRIDE * 2];  // 36864 B
    __nv_bfloat16* As = (__nv_bfloat16*)smraw;
    __nv_bfloat16* Bs = As + 128 * ASTRIDE;
    __nv_bfloat16* Cs = (__nv_bfloat16*)smraw;  // reused after compute

    int tid = threadIdx.x;
    int gbase = blockIdx.x * 4;     // 4 genes -> 128 output cols
    int cbase = blockIdx.y * 128;   // 128 cells

    const uint4* asrc = (const uint4*)(g_latb + (size_t)cbase * NLAT);
    const uint4* bsrc = (const uint4*)(g_lwb + (size_t)gbase * (NCOMP * NLAT));
#pragma unroll
    for (int i = 0; i < 4; i++) {
        int cid = i * 256 + tid;
        int row = cid >> 3, ch = cid & 7;
        *(uint4*)(As + row * ASTRIDE + ch * 8) = asrc[cid];
        *(uint4*)(Bs + row * ASTRIDE + ch * 8) = bsrc[cid];
    }
    __syncthreads();

    int wid = tid >> 5, lane = tid & 31;
    int wm = (wid & 3) * 32;
    int wn = (wid >> 2) * 64;
    int g = lane >> 2, t = lane & 3;

    float acc[2][8][4];
#pragma unroll
    for (int mt = 0; mt < 2; mt++)
#pragma unroll
        for (int nt = 0; nt < 8; nt++)
#pragma unroll
            for (int j = 0; j < 4; j++) acc[mt][nt][j] = 0.0f;

#pragma unroll
    for (int kc = 0; kc < 4; kc++) {
        int k0 = kc * 16;
        unsigned a[2][4];
#pragma unroll
        for (int mt = 0; mt < 2; mt++) {
            int r0 = wm + mt * 16 + g;
            a[mt][0] = *(const unsigned*)(As + (r0)     * ASTRIDE + k0 + 2 * t);
            a[mt][1] = *(const unsigned*)(As + (r0 + 8) * ASTRIDE + k0 + 2 * t);
            a[mt][2] = *(const unsigned*)(As + (r0)     * ASTRIDE + k0 + 2 * t + 8);
            a[mt][3] = *(const unsigned*)(As + (r0 + 8) * ASTRIDE + k0 + 2 * t + 8);
        }
        unsigned b[8][2];
#pragma unroll
        for (int nt = 0; nt < 8; nt++) {
            int n0 = wn + nt * 8 + g;
            b[nt][0] = *(const unsigned*)(Bs + n0 * ASTRIDE + k0 + 2 * t);
            b[nt][1] = *(const unsigned*)(Bs + n0 * ASTRIDE + k0 + 2 * t + 8);
        }
#pragma unroll
        for (int mt = 0; mt < 2; mt++)
#pragma unroll
            for (int nt = 0; nt < 8; nt++)
                mma_bf16(acc[mt][nt], a[mt], b[nt]);
    }
    __syncthreads();  // done with As/Bs; reuse as Cs

    // Stage to smem as bf16 with logit0 added.
#pragma unroll
    for (int nt = 0; nt < 8; nt++) {
        int col = wn + nt * 8 + 2 * t;
        float2 l0 = __bfloat1622float2(*(const __nv_bfloat162*)(g_l0b + gbase * NCOMP + col));
#pragma unroll
        for (int mt = 0; mt < 2; mt++) {
            int r0 = wm + mt * 16 + g;
            *(__nv_bfloat162*)(Cs + r0 * CSTRIDE + col) =
                __floats2bfloat162_rn(acc[mt][nt][0] + l0.x, acc[mt][nt][1] + l0.y);
            *(__nv_bfloat162*)(Cs + (r0 + 8) * CSTRIDE + col) =
                __floats2bfloat162_rn(acc[mt][nt][2] + l0.x, acc[mt][nt][3] + l0.y);
        }
    }
    __syncthreads();

    // Coalesced copy to global: 128 rows x 256B.
    size_t rowstride = (size_t)n_genes * NCOMP;
    __nv_bfloat16* dbase = g_deltab + (size_t)gbase * NCOMP;
#pragma unroll
    for (int it = 0; it < 8; it++) {
        int cid = it * 256 + tid;        // row = cid>>4, ch = cid&15
        int row = cid >> 4, ch = cid & 15;
        uint4 v = *(const uint4*)(Cs + row * CSTRIDE + ch * 8);
        *(uint4*)(dbase + (size_t)(cbase + row) * rowstride + ch * 8) = v;
    }

    // Per-pair LSE of bf16 logits (consistent with what k_mix reads).
#pragma unroll
    for (int it = 0; it < 2; it++) {
        int p = it * 256 + tid;          // 512 pairs: row = p>>2, gi = p&3
        int row = p >> 2, gi = p & 3;
        const __nv_bfloat162* crow = (const __nv_bfloat162*)(Cs + row * CSTRIDE + gi * 32);
        float s = 0.0f;
#pragma unroll
        for (int j = 0; j < 16; j++) {
            float2 f = __bfloat1622float2(crow[j]);
            s += __expf(f.x) + __expf(f.y);
        }
        g_ldenom[(size_t)(cbase + row) * n_genes + gbase + gi] = __logf(s);
    }
}

// ---------------- Poisson fragment-count likelihood ----------------
__global__ void k_poisson(int n_cells, int n_genes) {
    __shared__ float rw_s[8][NLAT];
    __shared__ float red[8];

    int gbase = blockIdx.x * 8;
    int cell = blockIdx.y * 256 + threadIdx.x;
    int tid = threadIdx.x;

    for (int i = tid; i < 8 * NLAT; i += 256) {
        int j = i / NLAT, l = i % NLAT;
        int g = gbase + j;
        rw_s[j][l] = (g < n_genes) ? g_grw[g * NLAT + l] : 0.0f;
    }
    __syncthreads();

    float lsum = 0.0f;
    if (cell < n_cells) {
        float acc[8] = {0, 0, 0, 0, 0, 0, 0, 0};
#pragma unroll 16
        for (int l = 0; l < NLAT; l++) {
            float lat = g_latT[l * n_cells + cell];
#pragma unroll
            for (int j = 0; j < 8; j++)
                acc[j] = fmaf(lat, rw_s[j][l], acc[j]);
        }
        float lib = g_lib[cell], ll = g_loglib[cell];
#pragma unroll
        for (int j = 0; j < 8; j++) {
            int g = gbase + j;
            if (g >= n_genes) continue;
            float rho = acc[j];
            float fe = g_rb[g] * __expf(rho) * lib;
            float cnt = g_counts[(size_t)cell * n_genes + g];
            float t = cnt * (g_logrb[g] + rho + ll) - fe;
            if (cnt > 1.5f) t -= lgammaf(cnt + 1.0f);
            lsum += t;
        }
    }
    for (int s = 16; s > 0; s >>= 1) lsum += __shfl_xor_sync(0xffffffffu, lsum, s);
    int wid = tid >> 5;
    if ((tid & 31) == 0) red[wid] = lsum;
    __syncthreads();
    if (tid == 0) {
        float s = 0.0f;
        for (int i = 0; i < 8; i++) s += red[i];
        atomicAdd(&g_acc, (double)s);
    }
}

// ---------------- Mixture likelihood: 8 cuts/warp, 4 lanes/cut, 8 comps/lane ----------------
__global__ void __launch_bounds__(256) k_mix(int n_cuts) {
    __shared__ float red[8];
    int tid = threadIdx.x;
    int lane = tid & 31;
    int wid = tid >> 5;
    int sub = lane >> 2;     // cut within batch of 8
    int q = lane & 3;        // comp quarter (8 comps)
    int gwarp = blockIdx.x * 8 + wid;
    int nwarps = gridDim.x * 8;
    int nbatch = (n_cuts + 7) >> 3;

    float local = 0.0f;
    for (int kb = gwarp; kb < nbatch; kb += nwarps) {
        int k = kb * 8 + sub;
        bool valid = k < n_cuts;
        uint2 rec = g_scut2[valid ? k : 0];
        int pair = (int)rec.x;
        int g = (int)(rec.y >> 16);
        float x = (float)(rec.y & 0xFFFFu) * (1.0f / 65535.0f);

        int tb = g * NCOMP + q * 8;
        const float4* lp = (const float4*)(g_loc + tb);
        const float4* sp = (const float4*)(g_isc + tb);
        const float4* wp = (const float4*)(g_twv + tb);
        float4 L0 = lp[0], L1 = lp[1];
        float4 S0 = sp[0], S1 = sp[1];
        float4 W0 = wp[0], W1 = wp[1];
        uint4 dv = *(const uint4*)(g_deltab + (size_t)pair * NCOMP + q * 8);
        const __nv_bfloat162* pv = (const __nv_bfloat162*)&dv;
        float2 f0 = __bfloat1622float2(pv[0]);
        float2 f1 = __bfloat1622float2(pv[1]);
        float2 f2 = __bfloat1622float2(pv[2]);
        float2 f3 = __bfloat1622float2(pv[3]);

        float e = 0.0f, z;
        z = (x - L0.x) * S0.x; e += __expf(fmaf(-0.5f * z, z, f0.x + W0.x));
        z = (x - L0.y) * S0.y; e += __expf(fmaf(-0.5f * z, z, f0.y + W0.y));
        z = (x - L0.z) * S0.z; e += __expf(fmaf(-0.5f * z, z, f1.x + W0.z));
        z = (x - L0.w) * S0.w; e += __expf(fmaf(-0.5f * z, z, f1.y + W0.w));
        z = (x - L1.x) * S1.x; e += __expf(fmaf(-0.5f * z, z, f2.x + W1.x));
        z = (x - L1.y) * S1.y; e += __expf(fmaf(-0.5f * z, z, f2.y + W1.y));
        z = (x - L1.z) * S1.z; e += __expf(fmaf(-0.5f * z, z, f3.x + W1.z));
        z = (x - L1.w) * S1.w; e += __expf(fmaf(-0.5f * z, z, f3.y + W1.w));

        e += __shfl_xor_sync(0xffffffffu, e, 1);
        e += __shfl_xor_sync(0xffffffffu, e, 2);

        if (q == 0 && valid) {
            float ld = g_ldenom[pair];
            local += __logf(fmaxf(e, 1e-37f)) - ld;
        }
    }
#pragma unroll
    for (int s = 16; s > 0; s >>= 1) local += __shfl_xor_sync(0xffffffffu, local, s);
    if (lane == 0) red[wid] = local;
    __syncthreads();
    if (tid == 0) {
        float s = 0.0f;
        for (int i = 0; i < 8; i++) s += red[i];
        atomicAdd(&g_acc, (double)s);
    }
}

__global__ void k_final(float* out) {
    out[0] = (float)(-g_acc);
}

extern "C" void kernel_launch(void* const* d_in, const int* in_sizes, int n_in,
                              void* d_out, int out_size) {
    const int*   frag_ix      = (const int*)d_in[0];
    const float* coord        = (const float*)d_in[1];
    const float* latent       = (const float*)d_in[2];
    const int*   genes_oi     = (const int*)d_in[3];
    const int*   cells_oi     = (const int*)d_in[4];
    const int*   cpx          = (const int*)d_in[5];
    const int*   cgx          = (const int*)d_in[6];
    const float* loc_w        = (const float*)d_in[9];
    const float* scale_w      = (const float*)d_in[10];
    const float* logit_w      = (const float*)d_in[11];
    const float* logit_weight = (const float*)d_in[12];
    const float* rho_weight   = (const float*)d_in[13];
    const float* rho_bias     = (const float*)d_in[14];
    const float* libsize      = (const float*)d_in[15];

    int n_frags = in_sizes[0];
    int n_cuts  = in_sizes[1];
    int n_genes = in_sizes[3];
    int n_cells = in_sizes[4];

    k_init<<<512, 256>>>(n_cells * n_genes);
    k_scatter<<<592, 256>>>(frag_ix, n_frags, cgx, n_cuts);
    k_scan<<<1, 1024>>>();
    k_ssort<<<(n_cuts + 255) / 256, 256>>>(cpx, cgx, coord, n_cuts);
    k_prep_tr<<<n_genes, 256>>>(loc_w, scale_w, logit_w, rho_weight, rho_bias, libsize,
                                latent, logit_weight, genes_oi, cells_oi, n_genes, n_cells);
    dim3 gg(n_genes / 4, n_cells / 128);
    k_gemm_mma<<<gg, 256>>>(n_cells, n_genes);
    dim3 gp((n_genes + 7) / 8, (n_cells + 255) / 256);
    k_poisson<<<gp, 256>>>(n_cells, n_genes);
    k_mix<<<1184, 256>>>(n_cuts);
    k_final<<<1, 1>>>((float*)d_out);
}

// round 14
// speedup vs baseline: 1.5549x; 1.2169x over previous
#include <cuda_runtime.h>
#include <cuda_bf16.h>
#include <math.h>

#define NCOMP 32
#define NLAT  64
#define MAXC  512
#define MAXG  4000
#define MAXCUT 1048576
#define NTILE 4000   // (n_genes/4) * (n_cells/128) for 4000x512

// Scratch (static device arrays — no runtime allocation)
static __device__ float  g_counts[MAXC * MAXG];                  // 8.2 MB
static __device__ float  g_loc[MAXG * NCOMP];                    // sigmoid(loc_w)
static __device__ float  g_isc[MAXG * NCOMP];                    // 1/scale
static __device__ float  g_twv[MAXG * NCOMP];                    // -log(scale)-0.5*log(2pi)
static __device__ __nv_bfloat16 g_l0b[MAXG * NCOMP];             // gathered logit_w bf16
static __device__ float  g_grw[MAXG * NLAT];                     // gathered rho_weight
static __device__ float  g_latT[NLAT * MAXC];                    // latent transposed [l][cell]
static __device__ __nv_bfloat16 g_latb[MAXC * NLAT];             // latent bf16 [cell][l]
static __device__ __nv_bfloat16 g_lwb[(size_t)MAXG * NCOMP * NLAT]; // weights bf16 [g][c][k] (K-major)
static __device__ float  g_logrb[MAXG];
static __device__ float  g_rb[MAXG];
static __device__ float  g_lib[MAXC];
static __device__ float  g_loglib[MAXC];
static __device__ int    g_hist[NTILE];                          // cuts per gemm tile
static __device__ int    g_tbase[NTILE];                         // tile start (stable)
static __device__ int    g_off[NTILE];                           // tile cursor (bumped)
static __device__ uint2  g_scut2[MAXCUT];                        // tile-sorted: {pair, gene<<16|coord16}
static __device__ double g_acc;

// ---------------- init ----------------
__global__ void k_init(int n) {
    int stride = gridDim.x * blockDim.x;
    for (int i = blockIdx.x * blockDim.x + threadIdx.x; i < n; i += stride)
        g_counts[i] = 0.0f;
    for (int i = blockIdx.x * blockDim.x + threadIdx.x; i < NTILE; i += stride)
        g_hist[i] = 0;
    if (blockIdx.x == 0 && threadIdx.x == 0) g_acc = 0.0;
}

// Fragment-count scatter (spread addresses -> fast atomics).
__global__ void k_scatter(const int* __restrict__ ix, int n_frags) {
    int i = blockIdx.x * blockDim.x + threadIdx.x;
    int stride = gridDim.x * blockDim.x;
    for (int k = i; k < n_frags; k += stride) atomicAdd(&g_counts[ix[k]], 1.0f);
}

// Tile histogram: fat blocks, smem hist, block-aggregated global atomics.
#define SORT_BLOCKS 64
__global__ void __launch_bounds__(256) k_hist2(const int* __restrict__ cpx, int n, int n_genes, int ncb) {
    __shared__ int h[NTILE];
    for (int i = threadIdx.x; i < NTILE; i += 256) h[i] = 0;
    __syncthreads();
    int chunk = (n + SORT_BLOCKS - 1) / SORT_BLOCKS;
    int s = blockIdx.x * chunk;
    int e = min(s + chunk, n);
    for (int i = s + threadIdx.x; i < e; i += 256) {
        unsigned pair = (unsigned)cpx[i];
        unsigned cell = pair / (unsigned)n_genes;
        unsigned gene = pair - cell * (unsigned)n_genes;
        int t = (int)((gene >> 2) * (unsigned)ncb + (cell >> 7));
        atomicAdd(&h[t], 1);
    }
    __syncthreads();
    for (int i = threadIdx.x; i < NTILE; i += 256)
        if (h[i]) atomicAdd(&g_hist[i], h[i]);
}

// Exclusive scan of g_hist -> g_tbase and g_off. One block, 1024 threads.
__global__ void k_scan() {
    __shared__ int wsum[32];
    int t = threadIdx.x, lane = t & 31, wid = t >> 5;
    int v[4], s = 0;
#pragma unroll
    for (int j = 0; j < 4; j++) {
        int b = t * 4 + j;
        v[j] = (b < NTILE) ? g_hist[b] : 0;
        s += v[j];
    }
    int inc = s;
#pragma unroll
    for (int o = 1; o < 32; o <<= 1) {
        int x = __shfl_up_sync(0xffffffffu, inc, o);
        if (lane >= o) inc += x;
    }
    if (lane == 31) wsum[wid] = inc;
    __syncthreads();
    if (wid == 0) {
        int w = wsum[lane];
        int wi = w;
#pragma unroll
        for (int o = 1; o < 32; o <<= 1) {
            int x = __shfl_up_sync(0xffffffffu, wi, o);
            if (lane >= o) wi += x;
        }
        wsum[lane] = wi - w;
    }
    __syncthreads();
    int base = wsum[wid] + inc - s;
#pragma unroll
    for (int j = 0; j < 4; j++) {
        int b = t * 4 + j;
        if (b < NTILE) { g_tbase[b] = base; g_off[b] = base; }
        base += v[j];
    }
}

// Placement: same chunking as k_hist2; smem counts -> block reservation -> scatter.
// Record carries the INDEPENDENT cgx gene (for mixture tables) + coord16.
__global__ void __launch_bounds__(256) k_ssort2(const int* __restrict__ cpx,
                                                const int* __restrict__ cgx,
                                                const float* __restrict__ coord,
                                                int n, int n_genes, int ncb) {
    __shared__ int h[NTILE];
    for (int i = threadIdx.x; i < NTILE; i += 256) h[i] = 0;
    __syncthreads();
    int chunk = (n + SORT_BLOCKS - 1) / SORT_BLOCKS;
    int s = blockIdx.x * chunk;
    int e = min(s + chunk, n);
    for (int i = s + threadIdx.x; i < e; i += 256) {
        unsigned pair = (unsigned)cpx[i];
        unsigned cell = pair / (unsigned)n_genes;
        unsigned gene = pair - cell * (unsigned)n_genes;
        int t = (int)((gene >> 2) * (unsigned)ncb + (cell >> 7));
        atomicAdd(&h[t], 1);
    }
    __syncthreads();
    for (int i = threadIdx.x; i < NTILE; i += 256) {
        int c = h[i];
        h[i] = c ? atomicAdd(&g_off[i], c) : 0;
    }
    __syncthreads();
    for (int i = s + threadIdx.x; i < e; i += 256) {
        unsigned pair = (unsigned)cpx[i];
        unsigned cell = pair / (unsigned)n_genes;
        unsigned gene = pair - cell * (unsigned)n_genes;
        int t = (int)((gene >> 2) * (unsigned)ncb + (cell >> 7));
        unsigned c16 = (unsigned)(coord[i] * 65535.0f + 0.5f);
        if (c16 > 65535u) c16 = 65535u;
        int pos = atomicAdd(&h[t], 1);
        g_scut2[pos] = make_uint2(pair, ((unsigned)cgx[i] << 16) | c16);
    }
}

// ---------------- prep + weight transpose (fused; grid = n_genes blocks of 256) ----------------
__global__ void k_prep_tr(const float* __restrict__ loc_w, const float* __restrict__ scale_w,
                          const float* __restrict__ logit_w, const float* __restrict__ rho_weight,
                          const float* __restrict__ rho_bias, const float* __restrict__ libsize,
                          const float* __restrict__ latent, const float* __restrict__ logit_weight,
                          const int* __restrict__ genes_oi, const int* __restrict__ cells_oi,
                          int n_genes, int n_cells) {
    __shared__ float ts[NLAT][NCOMP + 1];
    int g = blockIdx.x;
    int tg = genes_oi[g];
    const float4* src = (const float4*)(logit_weight + (size_t)tg * (NLAT * NCOMP));
    int tid = threadIdx.x;
#pragma unroll
    for (int it = 0; it < 2; it++) {
        int i = it * 256 + tid;
        float4 v = src[i];
        int k = i >> 3, c4 = (i & 7) * 4;
        ts[k][c4] = v.x; ts[k][c4 + 1] = v.y; ts[k][c4 + 2] = v.z; ts[k][c4 + 3] = v.w;
    }
    __syncthreads();
    __nv_bfloat162* dst = (__nv_bfloat162*)(g_lwb + (size_t)g * (NCOMP * NLAT));
#pragma unroll
    for (int it = 0; it < 4; it++) {
        int i = it * 256 + tid;
        int c = i >> 5, k2 = (i & 31) * 2;
        dst[i] = __floats2bfloat162_rn(ts[k2][c], ts[k2 + 1][c]);
    }

    int total = n_genes * NCOMP + n_genes * NLAT + n_genes + n_cells * NLAT + n_cells;
    int stride = gridDim.x * 256;
    for (int i = blockIdx.x * 256 + tid; i < total; i += stride) {
        int r = i;
        if (r < n_genes * NCOMP) {
            int gg = r / NCOMP, c = r % NCOMP;
            int tgg = genes_oi[gg];
            float lw = loc_w[(size_t)tgg * NCOMP + c];
            float sw = scale_w[(size_t)tgg * NCOMP + c];
            float lg = logit_w[(size_t)tgg * NCOMP + c];
            float scale = 1e-5f + expf(sw);
            g_loc[r] = 1.0f / (1.0f + expf(-lw));
            g_isc[r] = 1.0f / scale;
            g_twv[r] = -logf(scale) - 0.91893853320467274f;
            g_l0b[r] = __float2bfloat16(lg);
            continue;
        }
        r -= n_genes * NCOMP;
        if (r < n_genes * NLAT) {
            int gg = r / NLAT, l = r % NLAT;
            g_grw[r] = rho_weight[(size_t)genes_oi[gg] * NLAT + l];
            continue;
        }
        r -= n_genes * NLAT;
        if (r < n_genes) {
            float rb = rho_bias[genes_oi[r]];
            g_rb[r] = rb;
            g_logrb[r] = logf(rb);
            continue;
        }
        r -= n_genes;
        if (r < n_cells * NLAT) {
            int l = r / n_cells, cell = r % n_cells;
            float v = latent[(size_t)cell * NLAT + l];
            g_latT[r] = v;
            g_latb[(size_t)cell * NLAT + l] = __float2bfloat16(v);
            continue;
        }
        r -= n_cells * NLAT;
        {
            float lb = libsize[cells_oi[r]];
            g_lib[r] = lb;
            g_loglib[r] = logf(lb);
        }
    }
}

// ---------------- fused GEMM + mixture likelihood ----------------
// CTA = tile (4 genes x 128 cells). MMA computes raw delta into smem (bf16);
// the cut loop consumes it directly. Mixture tables + logit0 come from global
// (L2-resident 1.7MB) indexed by the record's cgx gene — exact reference semantics.
#define ASTRIDE 72   // padded A/B row stride (bf16)
#define CSTRIDE 136  // padded C stage row stride (bf16)
#define SM_BYTES 36864

__device__ __forceinline__ void mma_bf16(float* c, const unsigned* a, const unsigned* b) {
    asm volatile(
        "mma.sync.aligned.m16n8k16.row.col.f32.bf16.bf16.f32 "
        "{%0,%1,%2,%3}, {%4,%5,%6,%7}, {%8,%9}, {%0,%1,%2,%3};"
        : "+f"(c[0]), "+f"(c[1]), "+f"(c[2]), "+f"(c[3])
        : "r"(a[0]), "r"(a[1]), "r"(a[2]), "r"(a[3]), "r"(b[0]), "r"(b[1]));
}

__global__ void __launch_bounds__(256) k_gemm_mix(int n_cells, int n_genes) {
    __shared__ __align__(16) char smraw[SM_BYTES];
    __shared__ float red[8];
    __nv_bfloat16* As = (__nv_bfloat16*)smraw;
    __nv_bfloat16* Bs = As + 128 * ASTRIDE;
    __nv_bfloat16* Cs = (__nv_bfloat16*)smraw;          // reused after MMA

    int tid = threadIdx.x;
    int gbase = blockIdx.x * 4;     // 4 genes -> 128 delta cols
    int cbase = blockIdx.y * 128;   // 128 cells
    int ncb = n_cells >> 7;
    int tile = blockIdx.x * ncb + blockIdx.y;

    const uint4* asrc = (const uint4*)(g_latb + (size_t)cbase * NLAT);
    const uint4* bsrc = (const uint4*)(g_lwb + (size_t)gbase * (NCOMP * NLAT));
#pragma unroll
    for (int i = 0; i < 4; i++) {
        int cid = i * 256 + tid;
        int row = cid >> 3, ch = cid & 7;
        *(uint4*)(As + row * ASTRIDE + ch * 8) = asrc[cid];
        *(uint4*)(Bs + row * ASTRIDE + ch * 8) = bsrc[cid];
    }
    __syncthreads();

    int wid = tid >> 5, lane = tid & 31;
    int wm = (wid & 3) * 32;
    int wn = (wid >> 2) * 64;
    int g = lane >> 2, t = lane & 3;

    float acc[2][8][4];
#pragma unroll
    for (int mt = 0; mt < 2; mt++)
#pragma unroll
        for (int nt = 0; nt < 8; nt++)
#pragma unroll
            for (int j = 0; j < 4; j++) acc[mt][nt][j] = 0.0f;

#pragma unroll
    for (int kc = 0; kc < 4; kc++) {
        int k0 = kc * 16;
        unsigned a[2][4];
#pragma unroll
        for (int mt = 0; mt < 2; mt++) {
            int r0 = wm + mt * 16 + g;
            a[mt][0] = *(const unsigned*)(As + (r0)     * ASTRIDE + k0 + 2 * t);
            a[mt][1] = *(const unsigned*)(As + (r0 + 8) * ASTRIDE + k0 + 2 * t);
            a[mt][2] = *(const unsigned*)(As + (r0)     * ASTRIDE + k0 + 2 * t + 8);
            a[mt][3] = *(const unsigned*)(As + (r0 + 8) * ASTRIDE + k0 + 2 * t + 8);
        }
        unsigned b[8][2];
#pragma unroll
        for (int nt = 0; nt < 8; nt++) {
            int n0 = wn + nt * 8 + g;
            b[nt][0] = *(const unsigned*)(Bs + n0 * ASTRIDE + k0 + 2 * t);
            b[nt][1] = *(const unsigned*)(Bs + n0 * ASTRIDE + k0 + 2 * t + 8);
        }
#pragma unroll
        for (int mt = 0; mt < 2; mt++)
#pragma unroll
            for (int nt = 0; nt < 8; nt++)
                mma_bf16(acc[mt][nt], a[mt], b[nt]);
    }
    __syncthreads();  // As/Bs dead; stage Cs

    // Stage raw delta (bf16) into Cs. (logit0 added per-cut from cgx gene.)
#pragma unroll
    for (int nt = 0; nt < 8; nt++) {
        int col = wn + nt * 8 + 2 * t;
#pragma unroll
        for (int mt = 0; mt < 2; mt++) {
            int r0 = wm + mt * 16 + g;
            *(__nv_bfloat162*)(Cs + r0 * CSTRIDE + col) =
                __floats2bfloat162_rn(acc[mt][nt][0], acc[mt][nt][1]);
            *(__nv_bfloat162*)(Cs + (r0 + 8) * CSTRIDE + col) =
                __floats2bfloat162_rn(acc[mt][nt][2], acc[mt][nt][3]);
        }
    }
    __syncthreads();

    // Cut loop: teams of 4 lanes per cut, 8 comps per lane.
    // Warp-uniform trip count keeps the team shuffles convergent.
    int start = g_tbase[tile];
    int end = start + g_hist[tile];
    int sub = lane >> 2;     // team id within warp (8 cuts/warp)
    int q = lane & 3;        // comp quarter
    float local = 0.0f;
    for (int kb = start + wid * 8; kb < end; kb += 64) {
        int k = kb + sub;
        bool valid = k < end;
        uint2 rec = g_scut2[valid ? k : start];
        unsigned pair = rec.x;
        int gene = (int)(rec.y >> 16);                       // cgx gene (independent)
        float x = (float)(rec.y & 0xFFFFu) * (1.0f / 65535.0f);
        unsigned cell = pair / (unsigned)n_genes;
        int gi = (int)(pair - cell * (unsigned)n_genes) - gbase;
        int row = (int)cell - cbase;

        // 8 delta comps from smem (16B), 8 table comps from global (L2-hot).
        uint4 dv = *(const uint4*)(Cs + row * CSTRIDE + gi * 32 + q * 8);
        uint4 lv = *(const uint4*)(g_l0b + gene * NCOMP + q * 8);
        const __nv_bfloat162* pd = (const __nv_bfloat162*)&dv;
        const __nv_bfloat162* pl = (const __nv_bfloat162*)&lv;
        int tb = gene * NCOMP + q * 8;
        float4 L0 = *(const float4*)(g_loc + tb);
        float4 L1 = *(const float4*)(g_loc + tb + 4);
        float4 S0 = *(const float4*)(g_isc + tb);
        float4 S1 = *(const float4*)(g_isc + tb + 4);
        float4 W0 = *(const float4*)(g_twv + tb);
        float4 W1 = *(const float4*)(g_twv + tb + 4);

        float lg[8];
#pragma unroll
        for (int j = 0; j < 4; j++) {
            float2 d = __bfloat1622float2(pd[j]);
            float2 l = __bfloat1622float2(pl[j]);
            lg[2 * j] = d.x + l.x;
            lg[2 * j + 1] = d.y + l.y;
        }
        float num = 0.0f, den = 0.0f, z;
        den += __expf(lg[0]); z = (x - L0.x) * S0.x; num += __expf(fmaf(-0.5f * z, z, lg[0] + W0.x));
        den += __expf(lg[1]); z = (x - L0.y) * S0.y; num += __expf(fmaf(-0.5f * z, z, lg[1] + W0.y));
        den += __expf(lg[2]); z = (x - L0.z) * S0.z; num += __expf(fmaf(-0.5f * z, z, lg[2] + W0.z));
        den += __expf(lg[3]); z = (x - L0.w) * S0.w; num += __expf(fmaf(-0.5f * z, z, lg[3] + W0.w));
        den += __expf(lg[4]); z = (x - L1.x) * S1.x; num += __expf(fmaf(-0.5f * z, z, lg[4] + W1.x));
        den += __expf(lg[5]); z = (x - L1.y) * S1.y; num += __expf(fmaf(-0.5f * z, z, lg[5] + W1.y));
        den += __expf(lg[6]); z = (x - L1.z) * S1.z; num += __expf(fmaf(-0.5f * z, z, lg[6] + W1.z));
        den += __expf(lg[7]); z = (x - L1.w) * S1.w; num += __expf(fmaf(-0.5f * z, z, lg[7] + W1.w));

        num += __shfl_xor_sync(0xffffffffu, num, 1);
        num += __shfl_xor_sync(0xffffffffu, num, 2);
        den += __shfl_xor_sync(0xffffffffu, den, 1);
        den += __shfl_xor_sync(0xffffffffu, den, 2);

        if (q == 0 && valid)
            local += __logf(fmaxf(num, 1e-37f)) - __logf(den);
    }

    // Block reduce -> double accumulator.
#pragma unroll
    for (int s = 16; s > 0; s >>= 1) local += __shfl_xor_sync(0xffffffffu, local, s);
    if (lane == 0) red[wid] = local;
    __syncthreads();
    if (tid == 0) {
        float s = 0.0f;
        for (int i = 0; i < 8; i++) s += red[i];
        atomicAdd(&g_acc, (double)s);
    }
}

// ---------------- Poisson fragment-count likelihood ----------------
__global__ void k_poisson(int n_cells, int n_genes) {
    __shared__ float rw_s[8][NLAT];
    __shared__ float red[8];

    int gbase = blockIdx.x * 8;
    int cell = blockIdx.y * 256 + threadIdx.x;
    int tid = threadIdx.x;

    for (int i = tid; i < 8 * NLAT; i += 256) {
        int j = i / NLAT, l = i % NLAT;
        int g = gbase + j;
        rw_s[j][l] = (g < n_genes) ? g_grw[g * NLAT + l] : 0.0f;
    }
    __syncthreads();

    float lsum = 0.0f;
    if (cell < n_cells) {
        float acc[8] = {0, 0, 0, 0, 0, 0, 0, 0};
#pragma unroll 16
        for (int l = 0; l < NLAT; l++) {
            float lat = g_latT[l * n_cells + cell];
#pragma unroll
            for (int j = 0; j < 8; j++)
                acc[j] = fmaf(lat, rw_s[j][l], acc[j]);
        }
        float lib = g_lib[cell], ll = g_loglib[cell];
#pragma unroll
        for (int j = 0; j < 8; j++) {
            int g = gbase + j;
            if (g >= n_genes) continue;
            float rho = acc[j];
            float fe = g_rb[g] * __expf(rho) * lib;
            float cnt = g_counts[(size_t)cell * n_genes + g];
            float t = cnt * (g_logrb[g] + rho + ll) - fe;
            if (cnt > 1.5f) t -= lgammaf(cnt + 1.0f);
            lsum += t;
        }
    }
    for (int s = 16; s > 0; s >>= 1) lsum += __shfl_xor_sync(0xffffffffu, lsum, s);
    int wid = tid >> 5;
    if ((tid & 31) == 0) red[wid] = lsum;
    __syncthreads();
    if (tid == 0) {
        float s = 0.0f;
        for (int i = 0; i < 8; i++) s += red[i];
        atomicAdd(&g_acc, (double)s);
    }
}

__global__ void k_final(float* out) {
    out[0] = (float)(-g_acc);
}

extern "C" void kernel_launch(void* const* d_in, const int* in_sizes, int n_in,
                              void* d_out, int out_size) {
    const int*   frag_ix      = (const int*)d_in[0];
    const float* coord        = (const float*)d_in[1];
    const float* latent       = (const float*)d_in[2];
    const int*   genes_oi     = (const int*)d_in[3];
    const int*   cells_oi     = (const int*)d_in[4];
    const int*   cpx          = (const int*)d_in[5];
    const int*   cgx          = (const int*)d_in[6];
    const float* loc_w        = (const float*)d_in[9];
    const float* scale_w      = (const float*)d_in[10];
    const float* logit_w      = (const float*)d_in[11];
    const float* logit_weight = (const float*)d_in[12];
    const float* rho_weight   = (const float*)d_in[13];
    const float* rho_bias     = (const float*)d_in[14];
    const float* libsize      = (const float*)d_in[15];

    int n_frags = in_sizes[0];
    int n_cuts  = in_sizes[1];
    int n_genes = in_sizes[3];
    int n_cells = in_sizes[4];
    int ncb     = n_cells >> 7;

    k_init<<<512, 256>>>(n_cells * n_genes);
    k_scatter<<<592, 256>>>(frag_ix, n_frags);
    k_hist2<<<SORT_BLOCKS, 256>>>(cpx, n_cuts, n_genes, ncb);
    k_scan<<<1, 1024>>>();
    k_ssort2<<<SORT_BLOCKS, 256>>>(cpx, cgx, coord, n_cuts, n_genes, ncb);
    k_prep_tr<<<n_genes, 256>>>(loc_w, scale_w, logit_w, rho_weight, rho_bias, libsize,
                                latent, logit_weight, genes_oi, cells_oi, n_genes, n_cells);
    dim3 gg(n_genes / 4, ncb);
    k_gemm_mix<<<gg, 256>>>(n_cells, n_genes);
    dim3 gp((n_genes + 7) / 8, (n_cells + 255) / 256);
    k_poisson<<<gp, 256>>>(n_cells, n_genes);
    k_final<<<1, 1>>>((float*)d_out);
}